// round 1
// baseline (speedup 1.0000x reference)
#include <cuda_runtime.h>
#include <cstdint>

// Problem constants (fixed-shape problem; scratch sized statically)
#define NMAX   100352          // >= N = 100000
#define CIN    128
#define NHEADS 4

// -------- scratch (no allocations allowed) --------
__device__ float              g_V[CIN * 8];        // folded weight: [k][o], o=0..3 -> s_j heads, 4..7 -> s_i heads
__device__ float              g_sj[NMAX * 4];      // s_j[n][h]
__device__ float              g_si[NMAX * 4];      // s_i[n][h]
__device__ unsigned long long g_best[NMAX * 4];    // per (src, head): packed (ordf(alpha)<<32)|(~e)
__device__ int                g_mask[NMAX];        // node_mask

// orderable-uint mapping for float (monotone)
__device__ __forceinline__ unsigned ordf(float f) {
    unsigned u = __float_as_uint(f);
    return (u & 0x80000000u) ? ~u : (u | 0x80000000u);
}
__device__ __forceinline__ unsigned long long make_key(float a, unsigned e) {
    return ((unsigned long long)ordf(a) << 32) | (unsigned long long)(0xFFFFFFFFu - e);
}

// -------- K_init: zero best table + mask --------
__global__ void k_init(int N) {
    int i = blockIdx.x * blockDim.x + threadIdx.x;
    int tot = N * 4;
    if (i < tot) g_best[i] = 0ull;
    if (i < N)   g_mask[i] = 0;
}

// -------- K_V: fold weight (128x128) and att_weight (1,4,64) into V (128x8) --------
__global__ void k_fold(const float* __restrict__ weight, const float* __restrict__ att) {
    // 1024 outputs; 256 threads * 4 each
    int t = threadIdx.x;
    #pragma unroll
    for (int r = 0; r < 4; r++) {
        int idx = t * 4 + r;           // idx in [0,1024)
        int k = idx >> 3;              // row of weight
        int o = idx & 7;               // output column
        int h = o & 3;
        int base_att = h * 64 + ((o >= 4) ? 32 : 0);
        const float* wrow = weight + k * CIN + h * 32;
        float s = 0.f;
        #pragma unroll
        for (int c = 0; c < 32; c++) s += wrow[c] * att[base_att + c];
        g_V[k * 8 + o] = s;
    }
}

// -------- K_s: s = x @ V, one warp per node, float4 coalesced, shuffle tree-reduce --------
__global__ __launch_bounds__(256) void k_scores(const float* __restrict__ x, int N) {
    int lane   = threadIdx.x & 31;
    int warpId = (blockIdx.x * blockDim.x + threadIdx.x) >> 5;
    int nWarps = (gridDim.x * blockDim.x) >> 5;

    // each lane owns 4 rows of V (rows lane*4 .. lane*4+3), 8 cols each
    float4 Vj[4], Vi[4];
    #pragma unroll
    for (int r = 0; r < 4; r++) {
        const float4* vp = (const float4*)(g_V + (lane * 4 + r) * 8);
        Vj[r] = vp[0];
        Vi[r] = vp[1];
    }

    const float4* x4 = (const float4*)x;
    for (int n = warpId; n < N; n += nWarps) {
        float4 xv = x4[(size_t)n * 32 + lane];
        float acc[8];
        acc[0] = xv.x * Vj[0].x + xv.y * Vj[1].x + xv.z * Vj[2].x + xv.w * Vj[3].x;
        acc[1] = xv.x * Vj[0].y + xv.y * Vj[1].y + xv.z * Vj[2].y + xv.w * Vj[3].y;
        acc[2] = xv.x * Vj[0].z + xv.y * Vj[1].z + xv.z * Vj[2].z + xv.w * Vj[3].z;
        acc[3] = xv.x * Vj[0].w + xv.y * Vj[1].w + xv.z * Vj[2].w + xv.w * Vj[3].w;
        acc[4] = xv.x * Vi[0].x + xv.y * Vi[1].x + xv.z * Vi[2].x + xv.w * Vi[3].x;
        acc[5] = xv.x * Vi[0].y + xv.y * Vi[1].y + xv.z * Vi[2].y + xv.w * Vi[3].y;
        acc[6] = xv.x * Vi[0].z + xv.y * Vi[1].z + xv.z * Vi[2].z + xv.w * Vi[3].z;
        acc[7] = xv.x * Vi[0].w + xv.y * Vi[1].w + xv.z * Vi[2].w + xv.w * Vi[3].w;
        #pragma unroll
        for (int off = 16; off > 0; off >>= 1) {
            #pragma unroll
            for (int o = 0; o < 8; o++)
                acc[o] += __shfl_xor_sync(0xFFFFFFFFu, acc[o], off);
        }
        if (lane == 0) {
            ((float4*)g_sj)[n] = make_float4(acc[0], acc[1], acc[2], acc[3]);
            ((float4*)g_si)[n] = make_float4(acc[4], acc[5], acc[6], acc[7]);
        }
    }
}

// -------- K_argmax: per-edge, per-head atomicMax of packed key on src --------
__global__ __launch_bounds__(256) void k_argmax(const int* __restrict__ srcp,
                                                const int* __restrict__ dstp, int E) {
    int e = blockIdx.x * blockDim.x + threadIdx.x;
    if (e >= E) return;
    int s = srcp[e], d = dstp[e];
    float4 sj = ((const float4*)g_sj)[s];
    float4 si = ((const float4*)g_si)[d];
    unsigned long long* b = g_best + (size_t)s * 4;
    atomicMax(&b[0], make_key(sj.x + si.x, (unsigned)e));
    atomicMax(&b[1], make_key(sj.y + si.y, (unsigned)e));
    atomicMax(&b[2], make_key(sj.z + si.z, (unsigned)e));
    atomicMax(&b[3], make_key(sj.w + si.w, (unsigned)e));
}

// -------- K_select: edge is winner for head h iff stored id == e; mark dst mask --------
__global__ __launch_bounds__(256) void k_select(const int* __restrict__ srcp,
                                                const int* __restrict__ dstp, int E) {
    int e = blockIdx.x * blockDim.x + threadIdx.x;
    if (e >= E) return;
    int s = srcp[e], d = dstp[e];
    unsigned myid = 0xFFFFFFFFu - (unsigned)e;
    const unsigned long long* b = g_best + (size_t)s * 4;
    bool sel = ((unsigned)b[0] == myid) | ((unsigned)b[1] == myid) |
               ((unsigned)b[2] == myid) | ((unsigned)b[3] == myid);
    if (sel) g_mask[d] = 1;   // benign race: all writers write 1
}

// -------- K_out: edge_keep, node_mask floats, batch slices --------
__global__ __launch_bounds__(256) void k_out(const int* __restrict__ srcp,
                                             const int* __restrict__ dstp,
                                             const int* __restrict__ slices,
                                             float* __restrict__ out_keep,
                                             float* __restrict__ out_mask,
                                             float* __restrict__ out_slices,
                                             int E, int N) {
    int i = blockIdx.x * blockDim.x + threadIdx.x;
    if (i < E) {
        int s = srcp[i], d = dstp[i];
        out_keep[i] = (g_mask[s] & g_mask[d]) ? 1.0f : 0.0f;
    }
    if (i < N) out_mask[i] = g_mask[i] ? 1.0f : 0.0f;
    if (i == 0) {
        out_slices[0] = (float)slices[0];
        out_slices[1] = (float)slices[1];
    }
}

extern "C" void kernel_launch(void* const* d_in, const int* in_sizes, int n_in,
                              void* d_out, int out_size) {
    const float* x      = (const float*)d_in[0];
    const int*   eidx   = (const int*)d_in[1];
    const int*   slices = (const int*)d_in[2];
    const float* weight = (const float*)d_in[3];
    const float* att    = (const float*)d_in[4];

    int N = in_sizes[0] / CIN;
    int E = in_sizes[1] / 2;
    const int* srcp = eidx;
    const int* dstp = eidx + E;

    float* out = (float*)d_out;

    // x_out section is mathematically exactly zero (masked nodes are zeroed; unmasked
    // nodes receive only zero messages) -> memset covers it.
    size_t xout_elems = (size_t)N * CIN;
    cudaMemsetAsync(out, 0, xout_elems * sizeof(float), 0);

    if ((size_t)out_size < xout_elems + (size_t)E + (size_t)N + 2) {
        // Fallback: output is only x_out (all zeros) -> done.
        return;
    }

    float* out_keep   = out + xout_elems;
    float* out_mask   = out_keep + E;
    float* out_slices = out_mask + N;

    int initThreads = N * 4;
    k_init<<<(initThreads + 255) / 256, 256>>>(N);
    k_fold<<<1, 256>>>(weight, att);
    k_scores<<<832, 256>>>(x, N);                       // 6656 warps, ~15 nodes each
    k_argmax<<<(E + 255) / 256, 256>>>(srcp, dstp, E);
    k_select<<<(E + 255) / 256, 256>>>(srcp, dstp, E);
    int m = (E > N) ? E : N;
    k_out<<<(m + 255) / 256, 256>>>(srcp, dstp, slices, out_keep, out_mask, out_slices, E, N);
}

// round 2
// speedup vs baseline: 1.1583x; 1.1583x over previous
#include <cuda_runtime.h>
#include <cstdint>

// Problem constants (fixed-shape problem; scratch sized statically)
#define NMAX   100352          // >= N = 100000
#define CIN    128

// -------- scratch (no allocations allowed) --------
__device__ float              g_V[CIN * 8];        // folded weight: [k][o], o=0..3 -> s_j heads, 4..7 -> s_i heads
__device__ float              g_sj[NMAX * 4];      // s_j[n][h]
__device__ float              g_si[NMAX * 4];      // s_i[n][h]
__device__ unsigned long long g_best[NMAX * 4];    // per (src, head): packed (ordf(alpha)<<32)|(0xFFFFFFFF-e)
__device__ float              g_maskf[NMAX];       // node_mask as float 0/1

// orderable-uint mapping for float (monotone)
__device__ __forceinline__ unsigned ordf(float f) {
    unsigned u = __float_as_uint(f);
    return (u & 0x80000000u) ? ~u : (u | 0x80000000u);
}
__device__ __forceinline__ unsigned long long make_key(float a, unsigned e) {
    return ((unsigned long long)ordf(a) << 32) | (unsigned long long)(0xFFFFFFFFu - e);
}

// -------- K1: zero best table + mask, and fold weights into V (128x8) --------
__global__ __launch_bounds__(256) void k_init(const float* __restrict__ weight,
                                              const float* __restrict__ att, int N) {
    int i = blockIdx.x * blockDim.x + threadIdx.x;
    int tot = N * 4;
    if (i < tot) g_best[i] = 0ull;
    if (i < N)   g_maskf[i] = 0.0f;
    if (i < 1024) {
        int k = i >> 3;                // row of weight
        int o = i & 7;                 // output column (0..3 = s_j heads, 4..7 = s_i heads)
        int h = o & 3;
        int base_att = h * 64 + ((o >= 4) ? 32 : 0);
        const float* wrow = weight + k * CIN + h * 32;
        float s = 0.f;
        #pragma unroll
        for (int c = 0; c < 32; c++) s += wrow[c] * att[base_att + c];
        g_V[k * 8 + o] = s;
    }
}

// -------- K2: s = x @ V, one warp per node, float4 coalesced, shuffle tree-reduce --------
__global__ __launch_bounds__(256) void k_scores(const float* __restrict__ x, int N) {
    int lane   = threadIdx.x & 31;
    int warpId = (blockIdx.x * blockDim.x + threadIdx.x) >> 5;
    int nWarps = (gridDim.x * blockDim.x) >> 5;

    // each lane owns 4 rows of V (rows lane*4 .. lane*4+3), 8 cols each
    float4 Vj[4], Vi[4];
    #pragma unroll
    for (int r = 0; r < 4; r++) {
        const float4* vp = (const float4*)(g_V + (lane * 4 + r) * 8);
        Vj[r] = vp[0];
        Vi[r] = vp[1];
    }

    const float4* x4 = (const float4*)x;
    for (int n = warpId; n < N; n += nWarps) {
        float4 xv = x4[(size_t)n * 32 + lane];
        float acc[8];
        acc[0] = xv.x * Vj[0].x + xv.y * Vj[1].x + xv.z * Vj[2].x + xv.w * Vj[3].x;
        acc[1] = xv.x * Vj[0].y + xv.y * Vj[1].y + xv.z * Vj[2].y + xv.w * Vj[3].y;
        acc[2] = xv.x * Vj[0].z + xv.y * Vj[1].z + xv.z * Vj[2].z + xv.w * Vj[3].z;
        acc[3] = xv.x * Vj[0].w + xv.y * Vj[1].w + xv.z * Vj[2].w + xv.w * Vj[3].w;
        acc[4] = xv.x * Vi[0].x + xv.y * Vi[1].x + xv.z * Vi[2].x + xv.w * Vi[3].x;
        acc[5] = xv.x * Vi[0].y + xv.y * Vi[1].y + xv.z * Vi[2].y + xv.w * Vi[3].y;
        acc[6] = xv.x * Vi[0].z + xv.y * Vi[1].z + xv.z * Vi[2].z + xv.w * Vi[3].z;
        acc[7] = xv.x * Vi[0].w + xv.y * Vi[1].w + xv.z * Vi[2].w + xv.w * Vi[3].w;
        #pragma unroll
        for (int off = 16; off > 0; off >>= 1) {
            #pragma unroll
            for (int o = 0; o < 8; o++)
                acc[o] += __shfl_xor_sync(0xFFFFFFFFu, acc[o], off);
        }
        if (lane == 0) {
            ((float4*)g_sj)[n] = make_float4(acc[0], acc[1], acc[2], acc[3]);
            ((float4*)g_si)[n] = make_float4(acc[4], acc[5], acc[6], acc[7]);
        }
    }
}

// -------- K3: per-edge argmax via read-before-atomic; fused zero-fill of x_out --------
__global__ __launch_bounds__(256) void k_argmax(const int* __restrict__ srcp,
                                                const int* __restrict__ dstp,
                                                float4* __restrict__ out_zero,
                                                int zero_n4, int E) {
    int t = blockIdx.x * blockDim.x + threadIdx.x;

    // fire-and-forget zero-fill of the x_out region (overlaps DRAM writes with
    // the L2-bound atomic phase below)
    if (t < zero_n4) out_zero[t] = make_float4(0.f, 0.f, 0.f, 0.f);

    if (t >= E) return;
    int s = srcp[t], d = dstp[t];
    float4 sj = ((const float4*)g_sj)[s];
    float4 si = ((const float4*)g_si)[d];
    unsigned long long k0 = make_key(sj.x + si.x, (unsigned)t);
    unsigned long long k1 = make_key(sj.y + si.y, (unsigned)t);
    unsigned long long k2 = make_key(sj.z + si.z, (unsigned)t);
    unsigned long long k3 = make_key(sj.w + si.w, (unsigned)t);
    unsigned long long* b = g_best + (size_t)s * 4;
    // read-before-atomic: possibly-stale read only causes an extra (harmless) atomic
    if (k0 > b[0]) atomicMax(&b[0], k0);
    if (k1 > b[1]) atomicMax(&b[1], k1);
    if (k2 > b[2]) atomicMax(&b[2], k2);
    if (k3 > b[3]) atomicMax(&b[3], k3);
}

// -------- K4: node-parallel winner decode -> mark dst of winning edge --------
__global__ __launch_bounds__(256) void k_winner(const int* __restrict__ dstp, int N) {
    int i = blockIdx.x * blockDim.x + threadIdx.x;
    if (i >= N * 4) return;
    unsigned long long key = g_best[i];
    if (key != 0ull) {
        unsigned e = 0xFFFFFFFFu - (unsigned)key;   // low 32 bits hold 0xFFFFFFFF - e
        int d = dstp[e];
        g_maskf[d] = 1.0f;                          // benign race: all writers write 1.0
    }
}

// -------- K5: edge_keep, node_mask floats, batch slices --------
__global__ __launch_bounds__(256) void k_out(const int* __restrict__ srcp,
                                             const int* __restrict__ dstp,
                                             const int* __restrict__ slices,
                                             float* __restrict__ out_keep,
                                             float* __restrict__ out_mask,
                                             float* __restrict__ out_slices,
                                             int E, int N) {
    int i = blockIdx.x * blockDim.x + threadIdx.x;
    if (i < E) {
        out_keep[i] = g_maskf[srcp[i]] * g_maskf[dstp[i]];   // AND of {0,1} floats
    }
    if (i < N) out_mask[i] = g_maskf[i];
    if (i == 0) {
        out_slices[0] = (float)slices[0];
        out_slices[1] = (float)slices[1];
    }
}

extern "C" void kernel_launch(void* const* d_in, const int* in_sizes, int n_in,
                              void* d_out, int out_size) {
    const float* x      = (const float*)d_in[0];
    const int*   eidx   = (const int*)d_in[1];
    const int*   slices = (const int*)d_in[2];
    const float* weight = (const float*)d_in[3];
    const float* att    = (const float*)d_in[4];

    int N = in_sizes[0] / CIN;
    int E = in_sizes[1] / 2;
    const int* srcp = eidx;
    const int* dstp = eidx + E;

    float* out = (float*)d_out;
    size_t xout_elems = (size_t)N * CIN;

    if ((size_t)out_size < xout_elems + (size_t)E + (size_t)N + 2) {
        // Fallback: output is only x_out (mathematically all zeros)
        cudaMemsetAsync(out, 0, (size_t)out_size * sizeof(float), 0);
        return;
    }

    float* out_keep   = out + xout_elems;
    float* out_mask   = out_keep + E;
    float* out_slices = out_mask + N;

    int zero_n4 = (int)(xout_elems / 4);            // CIN=128 -> divisible by 4

    k_init<<<(N * 4 + 255) / 256, 256>>>(weight, att, N);
    k_scores<<<832, 256>>>(x, N);
    int k3threads = (E > zero_n4) ? E : zero_n4;
    k_argmax<<<(k3threads + 255) / 256, 256>>>(srcp, dstp, (float4*)out, zero_n4, E);
    k_winner<<<(N * 4 + 255) / 256, 256>>>(dstp, N);
    int m = (E > N) ? E : N;
    k_out<<<(m + 255) / 256, 256>>>(srcp, dstp, slices, out_keep, out_mask, out_slices, E, N);
}